// round 14
// baseline (speedup 1.0000x reference)
#include <cuda_runtime.h>
#include <cuda_fp16.h>
#include <cstdint>
#include <cstddef>

// Shapes: B=4, S=2048, D=2048, P=int(2048*1.333)=2729
#define BSD 8192
#define DD  2048
#define PD  2729
#define PPD 2816          // P padded to multiple of 128 (BN) and 64 (BK)
#define PH  (PPD / 2)     // 1408 half2-pairs per row
#define NPAIR ((PD + 1) / 2)   // 1365 real pairs
#define BB  4
#define SS  2048
#define MB  2048          // rows per batch (S)

// ---------------- scratch (device globals) ----------------------------------
__device__ __align__(256) __half g_xn [(size_t)BSD * DD];
__device__ __align__(256) __half g_wi [(size_t)PD * DD];
__device__ __align__(256) __half g_wf [(size_t)PD * DD];
__device__ __align__(256) __half g_wo [(size_t)PD * DD];
__device__ __align__(256) __half g_wc [(size_t)PD * DD];
__device__ __align__(256) __half g_wout[(size_t)DD * PPD];   // padded cols zeroed
// packed gates: [row][pair][z] as half2 (z: 0=i,1=f,2=o,3=c). 16B per (row,pair).
__device__ __align__(256) __half2 g_gates[(size_t)BSD * PH * 4];
__device__ __align__(256) __half g_act[(size_t)BSD * PPD];   // pad cols stay 0 (zero-init)

// ---------------- PTX helpers ------------------------------------------------
__device__ __forceinline__ uint32_t smem_u32(const void* p) {
    uint32_t a;
    asm("{ .reg .u64 t; cvta.to.shared.u64 t, %1; cvt.u32.u64 %0, t; }" : "=r"(a) : "l"(p));
    return a;
}
__device__ __forceinline__ void cp16(uint32_t dst, const void* src, int nbytes) {
    asm volatile("cp.async.cg.shared.global [%0], [%1], 16, %2;\n"
                 :: "r"(dst), "l"(src), "r"(nbytes));
}
__device__ __forceinline__ void cp_commit() { asm volatile("cp.async.commit_group;\n"); }
template<int N> __device__ __forceinline__ void cp_wait() {
    asm volatile("cp.async.wait_group %0;\n" :: "n"(N) : "memory");
}
__device__ __forceinline__ void ldsm4(uint32_t* r, uint32_t addr) {
    asm volatile("ldmatrix.sync.aligned.m8n8.x4.shared.b16 {%0,%1,%2,%3}, [%4];"
                 : "=r"(r[0]), "=r"(r[1]), "=r"(r[2]), "=r"(r[3]) : "r"(addr));
}
// m16n8k16 fp16 in, fp32 accum
__device__ __forceinline__ void mma16(float* c, const uint32_t* a, const uint32_t* b) {
    asm volatile(
        "mma.sync.aligned.m16n8k16.row.col.f32.f16.f16.f32 "
        "{%0,%1,%2,%3}, {%4,%5,%6,%7}, {%8,%9}, {%0,%1,%2,%3};\n"
        : "+f"(c[0]), "+f"(c[1]), "+f"(c[2]), "+f"(c[3])
        : "r"(a[0]), "r"(a[1]), "r"(a[2]), "r"(a[3]), "r"(b[0]), "r"(b[1]));
}

// ---------------- fast activations -------------------------------------------
__device__ __forceinline__ float f_ex2(float x) { float y; asm("ex2.approx.f32 %0, %1;" : "=f"(y) : "f"(x)); return y; }
__device__ __forceinline__ float f_rcp(float x) { float y; asm("rcp.approx.f32 %0, %1;" : "=f"(y) : "f"(x)); return y; }
__device__ __forceinline__ float f_tanh(float x) {
    x = fminf(fmaxf(x, -15.f), 15.f);
    float u = f_ex2(x * 2.885390082f);             // e^{2x}
    return (u - 1.f) * f_rcp(u + 1.f);
}
__device__ __forceinline__ float f_sig(float x) {
    float v = f_ex2(-x * 1.442695041f);
    return f_rcp(1.f + v);
}
__device__ __forceinline__ float gate_act(float z, bool tanhOnly) {
    if (tanhOnly) return f_tanh(z);
    float t = 15.f * f_tanh(z * (1.f / 15.f));     // soft cap
    return f_sig(t);
}

// ---------------- rmsnorm -> fp16 --------------------------------------------
__global__ void rmsnorm_kernel(const float* __restrict__ x, const float* __restrict__ w) {
    int row = blockIdx.x;
    int t = threadIdx.x;
    const float4* xr = reinterpret_cast<const float4*>(x + (size_t)row * DD);
    float4 v0 = xr[t], v1 = xr[t + 256];
    float ss = v0.x*v0.x + v0.y*v0.y + v0.z*v0.z + v0.w*v0.w
             + v1.x*v1.x + v1.y*v1.y + v1.z*v1.z + v1.w*v1.w;
    #pragma unroll
    for (int o = 16; o > 0; o >>= 1) ss += __shfl_xor_sync(0xffffffffu, ss, o);
    __shared__ float red[8];
    if ((t & 31) == 0) red[t >> 5] = ss;
    __syncthreads();
    float tot = red[0]+red[1]+red[2]+red[3]+red[4]+red[5]+red[6]+red[7];
    float r = rsqrtf(tot * (1.0f / DD) + 1e-6f);
    const float4* wr = reinterpret_cast<const float4*>(w);
    float4 w0 = wr[t], w1 = wr[t + 256];
    __half2* dst = reinterpret_cast<__half2*>(g_xn + (size_t)row * DD);
    dst[t*2  ]       = __floats2half2_rn(v0.x*r*w0.x, v0.y*r*w0.y);
    dst[t*2+1]       = __floats2half2_rn(v0.z*r*w0.z, v0.w*r*w0.w);
    dst[(t+256)*2  ] = __floats2half2_rn(v1.x*r*w1.x, v1.y*r*w1.y);
    dst[(t+256)*2+1] = __floats2half2_rn(v1.z*r*w1.z, v1.w*r*w1.w);
}

// ---------------- weight conversion (vectorized) -----------------------------
__global__ void convert_w_kernel(const float* __restrict__ W0, const float* __restrict__ W1,
                                 const float* __restrict__ W2, const float* __restrict__ W3) {
    size_t i4 = (size_t)blockIdx.x * blockDim.x + threadIdx.x;
    if (i4 >= (size_t)PD * DD / 4) return;
    int z = blockIdx.y;
    const float* src = (z == 0) ? W0 : (z == 1) ? W1 : (z == 2) ? W2 : W3;
    __half* dst = (z == 0) ? g_wi : (z == 1) ? g_wf : (z == 2) ? g_wo : g_wc;
    float4 v = reinterpret_cast<const float4*>(src)[i4];
    __half2 h0 = __floats2half2_rn(v.x, v.y);
    __half2 h1 = __floats2half2_rn(v.z, v.w);
    *reinterpret_cast<uint2*>(dst + i4 * 4) =
        make_uint2(*reinterpret_cast<uint32_t*>(&h0), *reinterpret_cast<uint32_t*>(&h1));
}
__global__ void pad_wout_kernel(const float* __restrict__ wout) {
    size_t i4 = (size_t)blockIdx.x * blockDim.x + threadIdx.x;
    if (i4 >= (size_t)DD * PPD / 4) return;
    int d = (int)(i4 / (PPD / 4));
    int p = (int)(i4 % (PPD / 4)) * 4;
    const float* src = wout + (size_t)d * PD + p;
    float a0 = (p     < PD) ? src[0] : 0.f;
    float a1 = (p + 1 < PD) ? src[1] : 0.f;
    float a2 = (p + 2 < PD) ? src[2] : 0.f;
    float a3 = (p + 3 < PD) ? src[3] : 0.f;
    __half2 h0 = __floats2half2_rn(a0, a1);
    __half2 h1 = __floats2half2_rn(a2, a3);
    *reinterpret_cast<uint2*>(g_wout + i4 * 4) =
        make_uint2(*reinterpret_cast<uint32_t*>(&h0), *reinterpret_cast<uint32_t*>(&h1));
}

// ---------------- fp16 TN GEMM (8 warps 4x2 of 32x64) ------------------------
// XOR-swizzled smem rows (128B): chunk c of row r at r*128 + ((c^(r&7))<<4).
// MODE 0 (gates): z = blockIdx.z; epilogue stores half2 into packed
//   g_gates[row][pair][z] — same store count/width as a flat plane.
// MODE 1 (out): mbase = first output row (per-batch launches).
template<int MODE>
__global__ __launch_bounds__(256, 2)
void gemm_fp16(const float* __restrict__ resid, float* __restrict__ outp,
               int Nreal, int KT, int lda, int ldb, int mbase)
{
    constexpr int BM = 128, BN = 128, BK = 64;
    constexpr int TILE_B = BM * 128;        // 16384 bytes per tile (A or B)
    constexpr int STG = 2 * TILE_B;         // 32768 bytes per stage
    extern __shared__ char dsm[];

    const int tid  = threadIdx.x;
    const int lane = tid & 31;
    const int wid  = tid >> 5;
    const int wm   = wid & 3;               // 4 warps along M (32 rows)
    const int wn   = wid >> 2;              // 2 warps along N (64 cols)
    const int m0   = mbase + blockIdx.y * BM;
    const int n0   = blockIdx.x * BN;

    const __half* A;
    const __half* Bw;
    int z = 0;
    bool actTanh = false;
    if (MODE == 0) {
        A = g_xn;
        z = blockIdx.z;
        Bw = (z == 0) ? g_wi : (z == 1) ? g_wf : (z == 2) ? g_wo : g_wc;
        actTanh = (z == 3);
    } else {
        A = g_act; Bw = g_wout;
    }

    const uint32_t sbase = smem_u32(dsm);

    // ---- fill() invariants ---------------------------------------------------
    const int tr = tid >> 3;                 // base row 0..31
    const int tc = tid & 7;                  // 16B chunk, constant
    const uint32_t offS = (uint32_t)(tr * 128 + ((tc ^ (tr & 7)) << 4));
    const __half* pA = A + (size_t)(m0 + tr) * lda + tc * 8;
    int nb[4];
    size_t dB[4];
    #pragma unroll
    for (int i = 0; i < 4; ++i) {
        int r = n0 + tr + i * 32;
        int ok = (MODE == 1) || (r < Nreal);
        nb[i] = ok ? 16 : 0;
        dB[i] = (size_t)(ok ? (size_t)i * 32 * ldb : 0);
    }
    const __half* pB = Bw + (size_t)(n0 + tr) * ldb + tc * 8;

    auto fill = [&](uint32_t stg) {
        uint32_t ab = stg + offS;
        #pragma unroll
        for (int i = 0; i < 4; ++i)
            cp16(ab + i * 4096, pA + (size_t)i * 32 * lda, 16);
        uint32_t bb = ab + TILE_B;
        #pragma unroll
        for (int i = 0; i < 4; ++i)
            cp16(bb + i * 4096, pB + dB[i], nb[i]);
        cp_commit();
        pA += BK;
        pB += BK;
    };

    float acc[2][8][4];
    #pragma unroll
    for (int im = 0; im < 2; ++im)
        #pragma unroll
        for (int in = 0; in < 8; ++in)
            #pragma unroll
            for (int j = 0; j < 4; ++j) acc[im][in][j] = 0.0f;

    // ---- precomputed ldmatrix addresses --------------------------------------
    const int l7 = lane & 7, l6 = lane & 6, l1 = lane & 1;
    const int a_row = ((lane >> 3) & 1) * 8 + l7;
    const int a_ch  = (lane >> 4);                   // 0/1
    const int b_row = ((lane >> 4) & 1) * 8 + l7;
    const int b_ch  = (lane >> 3) & 1;
    uint32_t baseA[2], baseB[4], dks[4];
    #pragma unroll
    for (int im = 0; im < 2; ++im)
        baseA[im] = (uint32_t)((wm * 32 + im * 16 + a_row) * 128 + ((a_ch ^ l1) << 4));
    #pragma unroll
    for (int ip = 0; ip < 4; ++ip)
        baseB[ip] = (uint32_t)(TILE_B + (wn * 64 + ip * 16 + b_row) * 128 + ((b_ch ^ l1) << 4));
    #pragma unroll
    for (int ks = 0; ks < 4; ++ks)
        dks[ks] = (uint32_t)(((2 * ks) ^ l6) << 4);

    const uint32_t stg0 = sbase, stg1 = sbase + STG, stg2 = sbase + 2 * STG;

    fill(stg0);
    fill(stg1);
    cp_wait<1>();
    __syncthreads();

    int s = 0, sf = 2;          // current stage id, next-fill stage id
    for (int kt = 0; kt < KT; ++kt) {
        if (kt + 2 < KT) {
            fill(sf == 0 ? stg0 : sf == 1 ? stg1 : stg2);
            if (++sf == 3) sf = 0;
        } else cp_commit();

        const uint32_t stA = (s == 0) ? stg0 : (s == 1) ? stg1 : stg2;

        #pragma unroll
        for (int ks = 0; ks < 4; ++ks) {
            const uint32_t d = dks[ks];
            uint32_t ra[2][4];
            #pragma unroll
            for (int im = 0; im < 2; ++im)
                ldsm4(ra[im], stA + baseA[im] + d);
            #pragma unroll
            for (int ip = 0; ip < 4; ++ip) {
                uint32_t r4[4];
                ldsm4(r4, stA + baseB[ip] + d);
                #pragma unroll
                for (int im = 0; im < 2; ++im) {
                    mma16(acc[im][2*ip    ], ra[im], r4);
                    mma16(acc[im][2*ip + 1], ra[im], r4 + 2);
                }
            }
        }
        cp_wait<1>();
        __syncthreads();
        if (++s == 3) s = 0;
    }

    // ---- epilogue ------------------------------------------------------------
    const int qr = lane >> 2;
    const int qc = lane & 3;
    #pragma unroll
    for (int im = 0; im < 2; ++im) {
        int row = m0 + wm * 32 + im * 16 + qr;
        #pragma unroll
        for (int in = 0; in < 8; ++in) {
            int col = n0 + wn * 64 + in * 8 + qc * 2;
            float* a = acc[im][in];
            if (MODE == 0) {
                float v0 = gate_act(a[0], actTanh);
                float v1 = gate_act(a[1], actTanh);
                float v2 = gate_act(a[2], actTanh);
                float v3 = gate_act(a[3], actTanh);
                int pair = col >> 1;             // col is even
                g_gates[((size_t)row * PH + pair) * 4 + z] = __floats2half2_rn(v0, v1);
                g_gates[((size_t)(row + 8) * PH + pair) * 4 + z] = __floats2half2_rn(v2, v3);
            } else {
                const float2 x0 = *reinterpret_cast<const float2*>(resid + (size_t)row * DD + col);
                const float2 x1 = *reinterpret_cast<const float2*>(resid + (size_t)(row + 8) * DD + col);
                *reinterpret_cast<float2*>(outp + (size_t)row * DD + col) =
                    make_float2(a[0] + x0.x, a[1] + x0.y);
                *reinterpret_cast<float2*>(outp + (size_t)(row + 8) * DD + col) =
                    make_float2(a[2] + x1.x, a[3] + x1.y);
            }
        }
    }
}

// ---------------- sequential scan over S (per batch, 2 chains/thread) --------
// one uint4 load per step delivers {i,f,o,c} for a PAIR of adjacent p chains.
__global__ void scan_kernel(int b, const float* __restrict__ h0, float* __restrict__ hfin) {
    int pp = blockIdx.x * blockDim.x + threadIdx.x;   // pair index
    if (pp >= NPAIR) return;
    int p0 = pp * 2, p1 = p0 + 1;
    float hA = h0[(size_t)b * PD + p0];
    float hB = (p1 < PD) ? h0[(size_t)b * PD + p1] : 0.f;

    const uint4* g = reinterpret_cast<const uint4*>(g_gates) + (size_t)b * SS * PH + pp;
    __half2* act = reinterpret_cast<__half2*>(g_act + (size_t)b * SS * PPD + p0);

    constexpr int PF = 8;
    uint4 buf[PF];
    #pragma unroll
    for (int j = 0; j < PF; ++j) buf[j] = g[(size_t)j * PH];

    #pragma unroll 8
    for (int s = 0; s < SS; ++s) {
        uint4 v = buf[s & (PF - 1)];
        int sn = s + PF;
        if (sn < SS) buf[s & (PF - 1)] = g[(size_t)sn * PH];
        float2 iv = __half22float2(*reinterpret_cast<__half2*>(&v.x));
        float2 fv = __half22float2(*reinterpret_cast<__half2*>(&v.y));
        float2 ov = __half22float2(*reinterpret_cast<__half2*>(&v.z));
        float2 cv = __half22float2(*reinterpret_cast<__half2*>(&v.w));
        hA = fmaf(fv.x, hA, iv.x * cv.x);         // c pre-tanh'ed
        hB = fmaf(fv.y, hB, iv.y * cv.y);
        act[(size_t)s * PH] = __floats2half2_rn(ov.x * f_tanh(hA), ov.y * f_tanh(hB));
    }
    if (hfin) {
        hfin[(size_t)b * PD + p0] = hA;
        if (p1 < PD) hfin[(size_t)b * PD + p1] = hB;
    }
}

// ---------------- streams/events (static init; fallback if creation fails) ---
struct Ctx {
    cudaStream_t s[3] = {};
    cudaEvent_t eF = nullptr, eW = nullptr, eX = nullptr;
    cudaEvent_t eD[3] = {};
    bool ok = false;
    Ctx() {
        bool good = true;
        for (int i = 0; i < 3; ++i)
            good = good && (cudaStreamCreateWithFlags(&s[i], cudaStreamNonBlocking) == cudaSuccess);
        auto mk = [&](cudaEvent_t* e) {
            good = good && (cudaEventCreateWithFlags(e, cudaEventDisableTiming) == cudaSuccess);
        };
        mk(&eF); mk(&eW); mk(&eX);
        for (int i = 0; i < 3; ++i) mk(&eD[i]);
        ok = good && (cudaDeviceSynchronize() == cudaSuccess);
    }
};
static Ctx g_ctx;

// ---------------- launch -----------------------------------------------------
extern "C" void kernel_launch(void* const* d_in, const int* in_sizes, int n_in,
                              void* d_out, int out_size) {
    const float* x    = (const float*)d_in[0];
    const float* h0   = (const float*)d_in[1];
    const float* Wi   = (const float*)d_in[2];
    const float* Wf   = (const float*)d_in[3];
    const float* Wo   = (const float*)d_in[4];
    const float* Wc   = (const float*)d_in[5];
    const float* Wout = (const float*)d_in[6];
    const float* lnw  = (const float*)d_in[7];
    float* out = (float*)d_out;
    float* hfin = nullptr;
    if (out_size >= BSD * DD + BB * PD) hfin = out + (size_t)BSD * DD;

    constexpr int SMEM_BYTES = 3 * 2 * 128 * 128;      // 98304 (3 stages, A+B)
    cudaFuncSetAttribute(gemm_fp16<0>, cudaFuncAttributeMaxDynamicSharedMemorySize, SMEM_BYTES);
    cudaFuncSetAttribute(gemm_fp16<1>, cudaFuncAttributeMaxDynamicSharedMemorySize, SMEM_BYTES);

    const int SCAN_GRID = (NPAIR + 63) / 64;           // 22 blocks

    if (!g_ctx.ok) {
        // ---- fallback: flat sequential path ----
        rmsnorm_kernel<<<BSD, 256>>>(x, lnw);
        convert_w_kernel<<<dim3(((size_t)PD * DD / 4 + 255) / 256, 4), 256>>>(Wi, Wf, Wo, Wc);
        pad_wout_kernel<<<((size_t)DD * PPD / 4 + 255) / 256, 256>>>(Wout);
        gemm_fp16<0><<<dim3(PPD / 128, BSD / 128, 4), 256, SMEM_BYTES>>>(
            nullptr, nullptr, PD, DD / 64, DD, DD, 0);
        for (int b = 0; b < BB; ++b)
            scan_kernel<<<SCAN_GRID, 64>>>(b, h0, hfin);
        gemm_fp16<1><<<dim3(DD / 128, BSD / 128), 256, SMEM_BYTES>>>(
            x, out, DD, 43, PPD, PPD, 0);
        return;
    }

    cudaStream_t s0 = g_ctx.s[0], s1 = g_ctx.s[1], s2 = g_ctx.s[2];

    // ---- prep (forked): converts on s0 || rmsnorm on default ----
    cudaEventRecord(g_ctx.eF, 0);
    cudaStreamWaitEvent(s0, g_ctx.eF, 0);
    convert_w_kernel<<<dim3(((size_t)PD * DD / 4 + 255) / 256, 4), 256, 0, s0>>>(Wi, Wf, Wo, Wc);
    pad_wout_kernel<<<((size_t)DD * PPD / 4 + 255) / 256, 256, 0, s0>>>(Wout);
    cudaEventRecord(g_ctx.eW, s0);

    rmsnorm_kernel<<<BSD, 256>>>(x, lnw);
    cudaEventRecord(g_ctx.eX, 0);

    // ---- per-batch chains: gates_b -> scan_b -> out_b (R10 schedule) ----
    cudaStreamWaitEvent(s0, g_ctx.eX, 0);
    cudaStreamWaitEvent(s1, g_ctx.eX, 0);
    cudaStreamWaitEvent(s1, g_ctx.eW, 0);
    cudaStreamWaitEvent(s2, g_ctx.eX, 0);
    cudaStreamWaitEvent(s2, g_ctx.eW, 0);
    cudaStreamWaitEvent(0,  g_ctx.eW, 0);

    cudaStream_t chain[3] = { s0, s1, s2 };
    for (int b = 1; b < BB; ++b) {
        cudaStream_t st = chain[b - 1];
        gemm_fp16<0><<<dim3(PPD / 128, MB / 128, 4), 256, SMEM_BYTES, st>>>(
            nullptr, nullptr, PD, DD / 64, DD, DD, b * MB);
        scan_kernel<<<SCAN_GRID, 64, 0, st>>>(b, h0, hfin);
        gemm_fp16<1><<<dim3(DD / 128, MB / 128), 256, SMEM_BYTES, st>>>(
            x, out, DD, 43, PPD, PPD, b * MB);
        cudaEventRecord(g_ctx.eD[b - 1], st);
    }
    // batch 0 on default stream
    gemm_fp16<0><<<dim3(PPD / 128, MB / 128, 4), 256, SMEM_BYTES>>>(
        nullptr, nullptr, PD, DD / 64, DD, DD, 0);
    scan_kernel<<<SCAN_GRID, 64>>>(0, h0, hfin);
    gemm_fp16<1><<<dim3(DD / 128, MB / 128), 256, SMEM_BYTES>>>(
        x, out, DD, 43, PPD, PPD, 0);

    // ---- join ----
    for (int i = 0; i < 3; ++i)
        cudaStreamWaitEvent(0, g_ctx.eD[i], 0);
}

// round 15
// speedup vs baseline: 1.0499x; 1.0499x over previous
#include <cuda_runtime.h>
#include <cuda_fp16.h>
#include <cstdint>
#include <cstddef>

// Shapes: B=4, S=2048, D=2048, P=int(2048*1.333)=2729
#define BSD 8192
#define DD  2048
#define PD  2729
#define PPD 2816          // P padded to multiple of 128 (BN) and 64 (BK)
#define PH  (PPD / 2)     // half2 pairs per row
#define NPAIR ((PD + 1) / 2)   // 1365 chain pairs
#define BB  4
#define SS  2048
#define MB  2048          // rows per batch (S)

// ---------------- scratch (device globals) ----------------------------------
__device__ __align__(256) __half g_xn [(size_t)BSD * DD];
__device__ __align__(256) __half g_wi [(size_t)PD * DD];
__device__ __align__(256) __half g_wf [(size_t)PD * DD];
__device__ __align__(256) __half g_wo [(size_t)PD * DD];
__device__ __align__(256) __half g_wc [(size_t)PD * DD];
__device__ __align__(256) __half g_wout[(size_t)DD * PPD];   // padded cols zeroed
__device__ __align__(256) __half g_gi [(size_t)BSD * PPD];
__device__ __align__(256) __half g_gf [(size_t)BSD * PPD];
__device__ __align__(256) __half g_go [(size_t)BSD * PPD];
__device__ __align__(256) __half g_gc [(size_t)BSD * PPD];
__device__ __align__(256) __half g_act[(size_t)BSD * PPD];   // col>=PD harmless: wout pad cols are 0

// ---------------- PTX helpers ------------------------------------------------
__device__ __forceinline__ uint32_t smem_u32(const void* p) {
    uint32_t a;
    asm("{ .reg .u64 t; cvta.to.shared.u64 t, %1; cvt.u32.u64 %0, t; }" : "=r"(a) : "l"(p));
    return a;
}
__device__ __forceinline__ void cp16(uint32_t dst, const void* src, int nbytes) {
    asm volatile("cp.async.cg.shared.global [%0], [%1], 16, %2;\n"
                 :: "r"(dst), "l"(src), "r"(nbytes));
}
__device__ __forceinline__ void cp_commit() { asm volatile("cp.async.commit_group;\n"); }
template<int N> __device__ __forceinline__ void cp_wait() {
    asm volatile("cp.async.wait_group %0;\n" :: "n"(N) : "memory");
}
__device__ __forceinline__ void ldsm4(uint32_t* r, uint32_t addr) {
    asm volatile("ldmatrix.sync.aligned.m8n8.x4.shared.b16 {%0,%1,%2,%3}, [%4];"
                 : "=r"(r[0]), "=r"(r[1]), "=r"(r[2]), "=r"(r[3]) : "r"(addr));
}
// m16n8k16 fp16 in, fp32 accum
__device__ __forceinline__ void mma16(float* c, const uint32_t* a, const uint32_t* b) {
    asm volatile(
        "mma.sync.aligned.m16n8k16.row.col.f32.f16.f16.f32 "
        "{%0,%1,%2,%3}, {%4,%5,%6,%7}, {%8,%9}, {%0,%1,%2,%3};\n"
        : "+f"(c[0]), "+f"(c[1]), "+f"(c[2]), "+f"(c[3])
        : "r"(a[0]), "r"(a[1]), "r"(a[2]), "r"(a[3]), "r"(b[0]), "r"(b[1]));
}

// ---------------- fast activations -------------------------------------------
__device__ __forceinline__ float f_ex2(float x) { float y; asm("ex2.approx.f32 %0, %1;" : "=f"(y) : "f"(x)); return y; }
__device__ __forceinline__ float f_rcp(float x) { float y; asm("rcp.approx.f32 %0, %1;" : "=f"(y) : "f"(x)); return y; }
__device__ __forceinline__ float f_tanh(float x) {
    x = fminf(fmaxf(x, -15.f), 15.f);
    float u = f_ex2(x * 2.885390082f);             // e^{2x}
    return (u - 1.f) * f_rcp(u + 1.f);
}
__device__ __forceinline__ float f_sig(float x) {
    float v = f_ex2(-x * 1.442695041f);
    return f_rcp(1.f + v);
}
__device__ __forceinline__ float gate_act(float z, bool tanhOnly) {
    if (tanhOnly) return f_tanh(z);
    float t = 15.f * f_tanh(z * (1.f / 15.f));     // soft cap
    return f_sig(t);
}

// ---------------- rmsnorm -> fp16 --------------------------------------------
__global__ void rmsnorm_kernel(const float* __restrict__ x, const float* __restrict__ w) {
    int row = blockIdx.x;
    int t = threadIdx.x;
    const float4* xr = reinterpret_cast<const float4*>(x + (size_t)row * DD);
    float4 v0 = xr[t], v1 = xr[t + 256];
    float ss = v0.x*v0.x + v0.y*v0.y + v0.z*v0.z + v0.w*v0.w
             + v1.x*v1.x + v1.y*v1.y + v1.z*v1.z + v1.w*v1.w;
    #pragma unroll
    for (int o = 16; o > 0; o >>= 1) ss += __shfl_xor_sync(0xffffffffu, ss, o);
    __shared__ float red[8];
    if ((t & 31) == 0) red[t >> 5] = ss;
    __syncthreads();
    float tot = red[0]+red[1]+red[2]+red[3]+red[4]+red[5]+red[6]+red[7];
    float r = rsqrtf(tot * (1.0f / DD) + 1e-6f);
    const float4* wr = reinterpret_cast<const float4*>(w);
    float4 w0 = wr[t], w1 = wr[t + 256];
    __half2* dst = reinterpret_cast<__half2*>(g_xn + (size_t)row * DD);
    dst[t*2  ]       = __floats2half2_rn(v0.x*r*w0.x, v0.y*r*w0.y);
    dst[t*2+1]       = __floats2half2_rn(v0.z*r*w0.z, v0.w*r*w0.w);
    dst[(t+256)*2  ] = __floats2half2_rn(v1.x*r*w1.x, v1.y*r*w1.y);
    dst[(t+256)*2+1] = __floats2half2_rn(v1.z*r*w1.z, v1.w*r*w1.w);
}

// ---------------- weight conversion (vectorized) -----------------------------
__global__ void convert_w_kernel(const float* __restrict__ W0, const float* __restrict__ W1,
                                 const float* __restrict__ W2, const float* __restrict__ W3) {
    size_t i4 = (size_t)blockIdx.x * blockDim.x + threadIdx.x;
    if (i4 >= (size_t)PD * DD / 4) return;
    int z = blockIdx.y;
    const float* src = (z == 0) ? W0 : (z == 1) ? W1 : (z == 2) ? W2 : W3;
    __half* dst = (z == 0) ? g_wi : (z == 1) ? g_wf : (z == 2) ? g_wo : g_wc;
    float4 v = reinterpret_cast<const float4*>(src)[i4];
    __half2 h0 = __floats2half2_rn(v.x, v.y);
    __half2 h1 = __floats2half2_rn(v.z, v.w);
    *reinterpret_cast<uint2*>(dst + i4 * 4) =
        make_uint2(*reinterpret_cast<uint32_t*>(&h0), *reinterpret_cast<uint32_t*>(&h1));
}
__global__ void pad_wout_kernel(const float* __restrict__ wout) {
    size_t i4 = (size_t)blockIdx.x * blockDim.x + threadIdx.x;
    if (i4 >= (size_t)DD * PPD / 4) return;
    int d = (int)(i4 / (PPD / 4));
    int p = (int)(i4 % (PPD / 4)) * 4;
    const float* src = wout + (size_t)d * PD + p;
    float a0 = (p     < PD) ? src[0] : 0.f;
    float a1 = (p + 1 < PD) ? src[1] : 0.f;
    float a2 = (p + 2 < PD) ? src[2] : 0.f;
    float a3 = (p + 3 < PD) ? src[3] : 0.f;
    __half2 h0 = __floats2half2_rn(a0, a1);
    __half2 h1 = __floats2half2_rn(a2, a3);
    *reinterpret_cast<uint2*>(g_wout + i4 * 4) =
        make_uint2(*reinterpret_cast<uint32_t*>(&h0), *reinterpret_cast<uint32_t*>(&h1));
}

// ---------------- fp16 TN GEMM (R10 config: 8 warps 4x2 of 32x64) ------------
// XOR-swizzled smem rows (128B): chunk c of row r at r*128 + ((c^(r&7))<<4).
// MODE 0 (gates): z = blockIdx.z, flat half2-plane stores (R10-identical).
// MODE 1 (out): mbase = first output row (per-batch launches).
template<int MODE>
__global__ __launch_bounds__(256, 2)
void gemm_fp16(const float* __restrict__ resid, float* __restrict__ outp,
               int Nreal, int KT, int lda, int ldb, int mbase)
{
    constexpr int BM = 128, BN = 128, BK = 64;
    constexpr int TILE_B = BM * 128;        // 16384 bytes per tile (A or B)
    constexpr int STG = 2 * TILE_B;         // 32768 bytes per stage
    extern __shared__ char dsm[];

    const int tid  = threadIdx.x;
    const int lane = tid & 31;
    const int wid  = tid >> 5;
    const int wm   = wid & 3;               // 4 warps along M (32 rows)
    const int wn   = wid >> 2;              // 2 warps along N (64 cols)
    const int m0   = mbase + blockIdx.y * BM;
    const int n0   = blockIdx.x * BN;

    const __half* A;
    const __half* Bw;
    __half* C = nullptr;
    bool actTanh = false;
    if (MODE == 0) {
        A = g_xn;
        int z = blockIdx.z;
        Bw = (z == 0) ? g_wi : (z == 1) ? g_wf : (z == 2) ? g_wo : g_wc;
        C  = (z == 0) ? g_gi : (z == 1) ? g_gf : (z == 2) ? g_go : g_gc;
        actTanh = (z == 3);
    } else {
        A = g_act; Bw = g_wout;
    }

    const uint32_t sbase = smem_u32(dsm);

    // ---- fill() invariants ---------------------------------------------------
    const int tr = tid >> 3;                 // base row 0..31
    const int tc = tid & 7;                  // 16B chunk, constant
    const uint32_t offS = (uint32_t)(tr * 128 + ((tc ^ (tr & 7)) << 4));
    const __half* pA = A + (size_t)(m0 + tr) * lda + tc * 8;
    int nb[4];
    size_t dB[4];
    #pragma unroll
    for (int i = 0; i < 4; ++i) {
        int r = n0 + tr + i * 32;
        int ok = (MODE == 1) || (r < Nreal);
        nb[i] = ok ? 16 : 0;
        dB[i] = (size_t)(ok ? (size_t)i * 32 * ldb : 0);
    }
    const __half* pB = Bw + (size_t)(n0 + tr) * ldb + tc * 8;

    auto fill = [&](uint32_t stg) {
        uint32_t ab = stg + offS;
        #pragma unroll
        for (int i = 0; i < 4; ++i)
            cp16(ab + i * 4096, pA + (size_t)i * 32 * lda, 16);
        uint32_t bb = ab + TILE_B;
        #pragma unroll
        for (int i = 0; i < 4; ++i)
            cp16(bb + i * 4096, pB + dB[i], nb[i]);
        cp_commit();
        pA += BK;
        pB += BK;
    };

    float acc[2][8][4];
    #pragma unroll
    for (int im = 0; im < 2; ++im)
        #pragma unroll
        for (int in = 0; in < 8; ++in)
            #pragma unroll
            for (int j = 0; j < 4; ++j) acc[im][in][j] = 0.0f;

    // ---- precomputed ldmatrix addresses --------------------------------------
    const int l7 = lane & 7, l6 = lane & 6, l1 = lane & 1;
    const int a_row = ((lane >> 3) & 1) * 8 + l7;
    const int a_ch  = (lane >> 4);                   // 0/1
    const int b_row = ((lane >> 4) & 1) * 8 + l7;
    const int b_ch  = (lane >> 3) & 1;
    uint32_t baseA[2], baseB[4], dks[4];
    #pragma unroll
    for (int im = 0; im < 2; ++im)
        baseA[im] = (uint32_t)((wm * 32 + im * 16 + a_row) * 128 + ((a_ch ^ l1) << 4));
    #pragma unroll
    for (int ip = 0; ip < 4; ++ip)
        baseB[ip] = (uint32_t)(TILE_B + (wn * 64 + ip * 16 + b_row) * 128 + ((b_ch ^ l1) << 4));
    #pragma unroll
    for (int ks = 0; ks < 4; ++ks)
        dks[ks] = (uint32_t)(((2 * ks) ^ l6) << 4);

    const uint32_t stg0 = sbase, stg1 = sbase + STG, stg2 = sbase + 2 * STG;

    fill(stg0);
    fill(stg1);
    cp_wait<1>();
    __syncthreads();

    int s = 0, sf = 2;          // current stage id, next-fill stage id
    for (int kt = 0; kt < KT; ++kt) {
        if (kt + 2 < KT) {
            fill(sf == 0 ? stg0 : sf == 1 ? stg1 : stg2);
            if (++sf == 3) sf = 0;
        } else cp_commit();

        const uint32_t stA = (s == 0) ? stg0 : (s == 1) ? stg1 : stg2;

        #pragma unroll
        for (int ks = 0; ks < 4; ++ks) {
            const uint32_t d = dks[ks];
            uint32_t ra[2][4];
            #pragma unroll
            for (int im = 0; im < 2; ++im)
                ldsm4(ra[im], stA + baseA[im] + d);
            #pragma unroll
            for (int ip = 0; ip < 4; ++ip) {
                uint32_t r4[4];
                ldsm4(r4, stA + baseB[ip] + d);
                #pragma unroll
                for (int im = 0; im < 2; ++im) {
                    mma16(acc[im][2*ip    ], ra[im], r4);
                    mma16(acc[im][2*ip + 1], ra[im], r4 + 2);
                }
            }
        }
        cp_wait<1>();
        __syncthreads();
        if (++s == 3) s = 0;
    }

    // ---- epilogue (R10-identical half2 plane stores) -------------------------
    const int qr = lane >> 2;
    const int qc = lane & 3;
    #pragma unroll
    for (int im = 0; im < 2; ++im) {
        int row = m0 + wm * 32 + im * 16 + qr;
        #pragma unroll
        for (int in = 0; in < 8; ++in) {
            int col = n0 + wn * 64 + in * 8 + qc * 2;
            float* a = acc[im][in];
            if (MODE == 0) {
                float v0 = gate_act(a[0], actTanh);
                float v1 = gate_act(a[1], actTanh);
                float v2 = gate_act(a[2], actTanh);
                float v3 = gate_act(a[3], actTanh);
                *reinterpret_cast<__half2*>(C + (size_t)row * PPD + col) =
                    __floats2half2_rn(v0, v1);
                *reinterpret_cast<__half2*>(C + (size_t)(row + 8) * PPD + col) =
                    __floats2half2_rn(v2, v3);
            } else {
                const float2 x0 = *reinterpret_cast<const float2*>(resid + (size_t)row * DD + col);
                const float2 x1 = *reinterpret_cast<const float2*>(resid + (size_t)(row + 8) * DD + col);
                *reinterpret_cast<float2*>(outp + (size_t)row * DD + col) =
                    make_float2(a[0] + x0.x, a[1] + x0.y);
                *reinterpret_cast<float2*>(outp + (size_t)(row + 8) * DD + col) =
                    make_float2(a[2] + x1.x, a[3] + x1.y);
            }
        }
    }
}

// ---------------- sequential scan over S (2 chains per thread) ---------------
// gate planes are half2-aligned: one 4B load per gate serves 2 adjacent chains
// -> 4 loads + 1 store per step (was 8 loads + 2 stores in R10).
__global__ void scan_kernel(int b, const float* __restrict__ h0, float* __restrict__ hfin) {
    int pp = blockIdx.x * blockDim.x + threadIdx.x;   // chain-pair index
    if (pp >= NPAIR) return;
    int p0 = pp * 2, p1 = p0 + 1;
    float hA = h0[(size_t)b * PD + p0];
    float hB = (p1 < PD) ? h0[(size_t)b * PD + p1] : 0.f;

    size_t base2 = ((size_t)b * SS * PPD + p0) >> 1;   // half2 index
    const __half2* pi = reinterpret_cast<const __half2*>(g_gi) + base2;
    const __half2* pf = reinterpret_cast<const __half2*>(g_gf) + base2;
    const __half2* po = reinterpret_cast<const __half2*>(g_go) + base2;
    const __half2* pc = reinterpret_cast<const __half2*>(g_gc) + base2;
    __half2* act = reinterpret_cast<__half2*>(g_act) + base2;

    constexpr int PF = 8;
    __half2 bi[PF], bf[PF], bo[PF], bc[PF];
    #pragma unroll
    for (int j = 0; j < PF; ++j) {
        size_t o = (size_t)j * PH;
        bi[j] = pi[o]; bf[j] = pf[o]; bo[j] = po[o]; bc[j] = pc[o];
    }
    #pragma unroll 8
    for (int s = 0; s < SS; ++s) {
        int slot = s & (PF - 1);
        float2 iv = __half22float2(bi[slot]);
        float2 fv = __half22float2(bf[slot]);
        float2 ov = __half22float2(bo[slot]);
        float2 cv = __half22float2(bc[slot]);
        int sn = s + PF;
        if (sn < SS) {
            size_t o = (size_t)sn * PH;
            bi[slot] = pi[o]; bf[slot] = pf[o]; bo[slot] = po[o]; bc[slot] = pc[o];
        }
        hA = fmaf(fv.x, hA, iv.x * cv.x);              // c pre-tanh'ed
        hB = fmaf(fv.y, hB, iv.y * cv.y);
        act[(size_t)s * PH] = __floats2half2_rn(ov.x * f_tanh(hA), ov.y * f_tanh(hB));
    }
    if (hfin) {
        hfin[(size_t)b * PD + p0] = hA;
        if (p1 < PD) hfin[(size_t)b * PD + p1] = hB;
    }
}

// ---------------- streams/events (static init; fallback if creation fails) ---
struct Ctx {
    cudaStream_t s[3] = {};
    cudaEvent_t eF = nullptr, eW = nullptr, eX = nullptr;
    cudaEvent_t eD[3] = {};
    bool ok = false;
    Ctx() {
        bool good = true;
        for (int i = 0; i < 3; ++i)
            good = good && (cudaStreamCreateWithFlags(&s[i], cudaStreamNonBlocking) == cudaSuccess);
        auto mk = [&](cudaEvent_t* e) {
            good = good && (cudaEventCreateWithFlags(e, cudaEventDisableTiming) == cudaSuccess);
        };
        mk(&eF); mk(&eW); mk(&eX);
        for (int i = 0; i < 3; ++i) mk(&eD[i]);
        ok = good && (cudaDeviceSynchronize() == cudaSuccess);
    }
};
static Ctx g_ctx;

// ---------------- launch -----------------------------------------------------
extern "C" void kernel_launch(void* const* d_in, const int* in_sizes, int n_in,
                              void* d_out, int out_size) {
    const float* x    = (const float*)d_in[0];
    const float* h0   = (const float*)d_in[1];
    const float* Wi   = (const float*)d_in[2];
    const float* Wf   = (const float*)d_in[3];
    const float* Wo   = (const float*)d_in[4];
    const float* Wc   = (const float*)d_in[5];
    const float* Wout = (const float*)d_in[6];
    const float* lnw  = (const float*)d_in[7];
    float* out = (float*)d_out;
    float* hfin = nullptr;
    if (out_size >= BSD * DD + BB * PD) hfin = out + (size_t)BSD * DD;

    constexpr int SMEM_BYTES = 3 * 2 * 128 * 128;      // 98304 (3 stages, A+B)
    cudaFuncSetAttribute(gemm_fp16<0>, cudaFuncAttributeMaxDynamicSharedMemorySize, SMEM_BYTES);
    cudaFuncSetAttribute(gemm_fp16<1>, cudaFuncAttributeMaxDynamicSharedMemorySize, SMEM_BYTES);

    const int SCAN_GRID = (NPAIR + 63) / 64;           // 22 blocks/batch

    if (!g_ctx.ok) {
        // ---- fallback: flat sequential path ----
        rmsnorm_kernel<<<BSD, 256>>>(x, lnw);
        convert_w_kernel<<<dim3(((size_t)PD * DD / 4 + 255) / 256, 4), 256>>>(Wi, Wf, Wo, Wc);
        pad_wout_kernel<<<((size_t)DD * PPD / 4 + 255) / 256, 256>>>(Wout);
        gemm_fp16<0><<<dim3(PPD / 128, BSD / 128, 4), 256, SMEM_BYTES>>>(
            nullptr, nullptr, PD, DD / 64, DD, DD, 0);
        for (int b = 0; b < BB; ++b)
            scan_kernel<<<SCAN_GRID, 64>>>(b, h0, hfin);
        gemm_fp16<1><<<dim3(DD / 128, BSD / 128), 256, SMEM_BYTES>>>(
            x, out, DD, 43, PPD, PPD, 0);
        return;
    }

    cudaStream_t s0 = g_ctx.s[0], s1 = g_ctx.s[1], s2 = g_ctx.s[2];

    // ---- prep (forked): converts on s0 || rmsnorm on default ----
    cudaEventRecord(g_ctx.eF, 0);
    cudaStreamWaitEvent(s0, g_ctx.eF, 0);
    convert_w_kernel<<<dim3(((size_t)PD * DD / 4 + 255) / 256, 4), 256, 0, s0>>>(Wi, Wf, Wo, Wc);
    pad_wout_kernel<<<((size_t)DD * PPD / 4 + 255) / 256, 256, 0, s0>>>(Wout);
    cudaEventRecord(g_ctx.eW, s0);

    rmsnorm_kernel<<<BSD, 256>>>(x, lnw);
    cudaEventRecord(g_ctx.eX, 0);

    // ---- per-batch chains: gates_b -> scan_b -> out_b (R10 schedule) ----
    cudaStreamWaitEvent(s0, g_ctx.eX, 0);
    cudaStreamWaitEvent(s1, g_ctx.eX, 0);
    cudaStreamWaitEvent(s1, g_ctx.eW, 0);
    cudaStreamWaitEvent(s2, g_ctx.eX, 0);
    cudaStreamWaitEvent(s2, g_ctx.eW, 0);
    cudaStreamWaitEvent(0,  g_ctx.eW, 0);

    cudaStream_t chain[3] = { s0, s1, s2 };
    for (int b = 1; b < BB; ++b) {
        cudaStream_t st = chain[b - 1];
        gemm_fp16<0><<<dim3(PPD / 128, MB / 128, 4), 256, SMEM_BYTES, st>>>(
            nullptr, nullptr, PD, DD / 64, DD, DD, b * MB);
        scan_kernel<<<SCAN_GRID, 64, 0, st>>>(b, h0, hfin);
        gemm_fp16<1><<<dim3(DD / 128, MB / 128), 256, SMEM_BYTES, st>>>(
            x, out, DD, 43, PPD, PPD, b * MB);
        cudaEventRecord(g_ctx.eD[b - 1], st);
    }
    // batch 0 on default stream
    gemm_fp16<0><<<dim3(PPD / 128, MB / 128, 4), 256, SMEM_BYTES>>>(
        nullptr, nullptr, PD, DD / 64, DD, DD, 0);
    scan_kernel<<<SCAN_GRID, 64>>>(0, h0, hfin);
    gemm_fp16<1><<<dim3(DD / 128, MB / 128), 256, SMEM_BYTES>>>(
        x, out, DD, 43, PPD, PPD, 0);

    // ---- join ----
    for (int i = 0; i < 3; ++i)
        cudaStreamWaitEvent(0, g_ctx.eD[i], 0);
}

// round 16
// speedup vs baseline: 1.1147x; 1.0617x over previous
#include <cuda_runtime.h>
#include <cuda_fp16.h>
#include <cstdint>
#include <cstddef>

// Shapes: B=4, S=2048, D=2048, P=int(2048*1.333)=2729
#define BSD 8192
#define DD  2048
#define PD  2729
#define PPD 2816          // P padded to multiple of 128 (BN) and 64 (BK)
#define BB  4
#define SS  2048
#define MB  2048          // rows per batch (S)

// ---------------- scratch (device globals) ----------------------------------
__device__ __align__(256) __half g_xn [(size_t)BSD * DD];
__device__ __align__(256) __half g_wi [(size_t)PD * DD];
__device__ __align__(256) __half g_wf [(size_t)PD * DD];
__device__ __align__(256) __half g_wo [(size_t)PD * DD];
__device__ __align__(256) __half g_wc [(size_t)PD * DD];
__device__ __align__(256) __half g_wout[(size_t)DD * PPD];   // padded cols zeroed
__device__ __align__(256) __half g_gi [(size_t)BSD * PPD];
__device__ __align__(256) __half g_gf [(size_t)BSD * PPD];
__device__ __align__(256) __half g_go [(size_t)BSD * PPD];
__device__ __align__(256) __half g_gc [(size_t)BSD * PPD];
__device__ __align__(256) __half g_act[(size_t)BSD * PPD];   // pad cols stay 0 (zero-init)

// ---------------- PTX helpers ------------------------------------------------
__device__ __forceinline__ uint32_t smem_u32(const void* p) {
    uint32_t a;
    asm("{ .reg .u64 t; cvta.to.shared.u64 t, %1; cvt.u32.u64 %0, t; }" : "=r"(a) : "l"(p));
    return a;
}
__device__ __forceinline__ void cp16(uint32_t dst, const void* src, int nbytes) {
    asm volatile("cp.async.cg.shared.global [%0], [%1], 16, %2;\n"
                 :: "r"(dst), "l"(src), "r"(nbytes));
}
__device__ __forceinline__ void cp_commit() { asm volatile("cp.async.commit_group;\n"); }
template<int N> __device__ __forceinline__ void cp_wait() {
    asm volatile("cp.async.wait_group %0;\n" :: "n"(N) : "memory");
}
__device__ __forceinline__ void ldsm4(uint32_t* r, uint32_t addr) {
    asm volatile("ldmatrix.sync.aligned.m8n8.x4.shared.b16 {%0,%1,%2,%3}, [%4];"
                 : "=r"(r[0]), "=r"(r[1]), "=r"(r[2]), "=r"(r[3]) : "r"(addr));
}
// m16n8k16 fp16 in, fp32 accum
__device__ __forceinline__ void mma16(float* c, const uint32_t* a, const uint32_t* b) {
    asm volatile(
        "mma.sync.aligned.m16n8k16.row.col.f32.f16.f16.f32 "
        "{%0,%1,%2,%3}, {%4,%5,%6,%7}, {%8,%9}, {%0,%1,%2,%3};\n"
        : "+f"(c[0]), "+f"(c[1]), "+f"(c[2]), "+f"(c[3])
        : "r"(a[0]), "r"(a[1]), "r"(a[2]), "r"(a[3]), "r"(b[0]), "r"(b[1]));
}

// ---------------- fast activations -------------------------------------------
__device__ __forceinline__ float f_ex2(float x) { float y; asm("ex2.approx.f32 %0, %1;" : "=f"(y) : "f"(x)); return y; }
__device__ __forceinline__ float f_rcp(float x) { float y; asm("rcp.approx.f32 %0, %1;" : "=f"(y) : "f"(x)); return y; }
__device__ __forceinline__ float f_tanh(float x) {
    x = fminf(fmaxf(x, -15.f), 15.f);
    float u = f_ex2(x * 2.885390082f);             // e^{2x}
    return (u - 1.f) * f_rcp(u + 1.f);
}
__device__ __forceinline__ float f_sig(float x) {
    float v = f_ex2(-x * 1.442695041f);
    return f_rcp(1.f + v);
}
__device__ __forceinline__ float gate_act(float z, bool tanhOnly) {
    if (tanhOnly) return f_tanh(z);
    float t = 15.f * f_tanh(z * (1.f / 15.f));     // soft cap
    return f_sig(t);
}

// ---------------- rmsnorm -> fp16 (per-batch: rowbase) -----------------------
__global__ void rmsnorm_kernel(const float* __restrict__ x, const float* __restrict__ w,
                               int rowbase) {
    int row = rowbase + blockIdx.x;
    int t = threadIdx.x;
    const float4* xr = reinterpret_cast<const float4*>(x + (size_t)row * DD);
    float4 v0 = xr[t], v1 = xr[t + 256];
    float ss = v0.x*v0.x + v0.y*v0.y + v0.z*v0.z + v0.w*v0.w
             + v1.x*v1.x + v1.y*v1.y + v1.z*v1.z + v1.w*v1.w;
    #pragma unroll
    for (int o = 16; o > 0; o >>= 1) ss += __shfl_xor_sync(0xffffffffu, ss, o);
    __shared__ float red[8];
    if ((t & 31) == 0) red[t >> 5] = ss;
    __syncthreads();
    float tot = red[0]+red[1]+red[2]+red[3]+red[4]+red[5]+red[6]+red[7];
    float r = rsqrtf(tot * (1.0f / DD) + 1e-6f);
    const float4* wr = reinterpret_cast<const float4*>(w);
    float4 w0 = wr[t], w1 = wr[t + 256];
    __half2* dst = reinterpret_cast<__half2*>(g_xn + (size_t)row * DD);
    dst[t*2  ]       = __floats2half2_rn(v0.x*r*w0.x, v0.y*r*w0.y);
    dst[t*2+1]       = __floats2half2_rn(v0.z*r*w0.z, v0.w*r*w0.w);
    dst[(t+256)*2  ] = __floats2half2_rn(v1.x*r*w1.x, v1.y*r*w1.y);
    dst[(t+256)*2+1] = __floats2half2_rn(v1.z*r*w1.z, v1.w*r*w1.w);
}

// ---------------- weight conversion (vectorized) -----------------------------
__global__ void convert_w_kernel(const float* __restrict__ W0, const float* __restrict__ W1,
                                 const float* __restrict__ W2, const float* __restrict__ W3) {
    size_t i4 = (size_t)blockIdx.x * blockDim.x + threadIdx.x;
    if (i4 >= (size_t)PD * DD / 4) return;
    int z = blockIdx.y;
    const float* src = (z == 0) ? W0 : (z == 1) ? W1 : (z == 2) ? W2 : W3;
    __half* dst = (z == 0) ? g_wi : (z == 1) ? g_wf : (z == 2) ? g_wo : g_wc;
    float4 v = reinterpret_cast<const float4*>(src)[i4];
    __half2 h0 = __floats2half2_rn(v.x, v.y);
    __half2 h1 = __floats2half2_rn(v.z, v.w);
    *reinterpret_cast<uint2*>(dst + i4 * 4) =
        make_uint2(*reinterpret_cast<uint32_t*>(&h0), *reinterpret_cast<uint32_t*>(&h1));
}
__global__ void pad_wout_kernel(const float* __restrict__ wout) {
    size_t i4 = (size_t)blockIdx.x * blockDim.x + threadIdx.x;
    if (i4 >= (size_t)DD * PPD / 4) return;
    int d = (int)(i4 / (PPD / 4));
    int p = (int)(i4 % (PPD / 4)) * 4;
    const float* src = wout + (size_t)d * PD + p;
    float a0 = (p     < PD) ? src[0] : 0.f;
    float a1 = (p + 1 < PD) ? src[1] : 0.f;
    float a2 = (p + 2 < PD) ? src[2] : 0.f;
    float a3 = (p + 3 < PD) ? src[3] : 0.f;
    __half2 h0 = __floats2half2_rn(a0, a1);
    __half2 h1 = __floats2half2_rn(a2, a3);
    *reinterpret_cast<uint2*>(g_wout + i4 * 4) =
        make_uint2(*reinterpret_cast<uint32_t*>(&h0), *reinterpret_cast<uint32_t*>(&h1));
}

// ---------------- fp16 TN GEMM (R10 config: 8 warps 4x2 of 32x64) ------------
// XOR-swizzled smem rows (128B): chunk c of row r at r*128 + ((c^(r&7))<<4).
// MODE 0 (gates): z = blockIdx.z, flat half2-plane stores.
// MODE 1 (out): mbase = first output row (per-batch launches).
template<int MODE>
__global__ __launch_bounds__(256, 2)
void gemm_fp16(const float* __restrict__ resid, float* __restrict__ outp,
               int Nreal, int KT, int lda, int ldb, int mbase)
{
    constexpr int BM = 128, BN = 128, BK = 64;
    constexpr int TILE_B = BM * 128;        // 16384 bytes per tile (A or B)
    constexpr int STG = 2 * TILE_B;         // 32768 bytes per stage
    extern __shared__ char dsm[];

    const int tid  = threadIdx.x;
    const int lane = tid & 31;
    const int wid  = tid >> 5;
    const int wm   = wid & 3;               // 4 warps along M (32 rows)
    const int wn   = wid >> 2;              // 2 warps along N (64 cols)
    const int m0   = mbase + blockIdx.y * BM;
    const int n0   = blockIdx.x * BN;

    const __half* A;
    const __half* Bw;
    __half* C = nullptr;
    bool actTanh = false;
    if (MODE == 0) {
        A = g_xn;
        int z = blockIdx.z;
        Bw = (z == 0) ? g_wi : (z == 1) ? g_wf : (z == 2) ? g_wo : g_wc;
        C  = (z == 0) ? g_gi : (z == 1) ? g_gf : (z == 2) ? g_go : g_gc;
        actTanh = (z == 3);
    } else {
        A = g_act; Bw = g_wout;
    }

    const uint32_t sbase = smem_u32(dsm);

    // ---- fill() invariants ---------------------------------------------------
    const int tr = tid >> 3;                 // base row 0..31
    const int tc = tid & 7;                  // 16B chunk, constant
    const uint32_t offS = (uint32_t)(tr * 128 + ((tc ^ (tr & 7)) << 4));
    const __half* pA = A + (size_t)(m0 + tr) * lda + tc * 8;
    int nb[4];
    size_t dB[4];
    #pragma unroll
    for (int i = 0; i < 4; ++i) {
        int r = n0 + tr + i * 32;
        int ok = (MODE == 1) || (r < Nreal);
        nb[i] = ok ? 16 : 0;
        dB[i] = (size_t)(ok ? (size_t)i * 32 * ldb : 0);
    }
    const __half* pB = Bw + (size_t)(n0 + tr) * ldb + tc * 8;

    auto fill = [&](uint32_t stg) {
        uint32_t ab = stg + offS;
        #pragma unroll
        for (int i = 0; i < 4; ++i)
            cp16(ab + i * 4096, pA + (size_t)i * 32 * lda, 16);
        uint32_t bb = ab + TILE_B;
        #pragma unroll
        for (int i = 0; i < 4; ++i)
            cp16(bb + i * 4096, pB + dB[i], nb[i]);
        cp_commit();
        pA += BK;
        pB += BK;
    };

    float acc[2][8][4];
    #pragma unroll
    for (int im = 0; im < 2; ++im)
        #pragma unroll
        for (int in = 0; in < 8; ++in)
            #pragma unroll
            for (int j = 0; j < 4; ++j) acc[im][in][j] = 0.0f;

    // ---- precomputed ldmatrix addresses --------------------------------------
    const int l7 = lane & 7, l6 = lane & 6, l1 = lane & 1;
    const int a_row = ((lane >> 3) & 1) * 8 + l7;
    const int a_ch  = (lane >> 4);                   // 0/1
    const int b_row = ((lane >> 4) & 1) * 8 + l7;
    const int b_ch  = (lane >> 3) & 1;
    uint32_t baseA[2], baseB[4], dks[4];
    #pragma unroll
    for (int im = 0; im < 2; ++im)
        baseA[im] = (uint32_t)((wm * 32 + im * 16 + a_row) * 128 + ((a_ch ^ l1) << 4));
    #pragma unroll
    for (int ip = 0; ip < 4; ++ip)
        baseB[ip] = (uint32_t)(TILE_B + (wn * 64 + ip * 16 + b_row) * 128 + ((b_ch ^ l1) << 4));
    #pragma unroll
    for (int ks = 0; ks < 4; ++ks)
        dks[ks] = (uint32_t)(((2 * ks) ^ l6) << 4);

    const uint32_t stg0 = sbase, stg1 = sbase + STG, stg2 = sbase + 2 * STG;

    fill(stg0);
    fill(stg1);
    cp_wait<1>();
    __syncthreads();

    int s = 0, sf = 2;          // current stage id, next-fill stage id
    for (int kt = 0; kt < KT; ++kt) {
        if (kt + 2 < KT) {
            fill(sf == 0 ? stg0 : sf == 1 ? stg1 : stg2);
            if (++sf == 3) sf = 0;
        } else cp_commit();

        const uint32_t stA = (s == 0) ? stg0 : (s == 1) ? stg1 : stg2;

        #pragma unroll
        for (int ks = 0; ks < 4; ++ks) {
            const uint32_t d = dks[ks];
            uint32_t ra[2][4];
            #pragma unroll
            for (int im = 0; im < 2; ++im)
                ldsm4(ra[im], stA + baseA[im] + d);
            #pragma unroll
            for (int ip = 0; ip < 4; ++ip) {
                uint32_t r4[4];
                ldsm4(r4, stA + baseB[ip] + d);
                #pragma unroll
                for (int im = 0; im < 2; ++im) {
                    mma16(acc[im][2*ip    ], ra[im], r4);
                    mma16(acc[im][2*ip + 1], ra[im], r4 + 2);
                }
            }
        }
        cp_wait<1>();
        __syncthreads();
        if (++s == 3) s = 0;
    }

    // ---- epilogue ------------------------------------------------------------
    const int qr = lane >> 2;
    const int qc = lane & 3;
    #pragma unroll
    for (int im = 0; im < 2; ++im) {
        int row = m0 + wm * 32 + im * 16 + qr;
        #pragma unroll
        for (int in = 0; in < 8; ++in) {
            int col = n0 + wn * 64 + in * 8 + qc * 2;
            float* a = acc[im][in];
            if (MODE == 0) {
                float v0 = gate_act(a[0], actTanh);
                float v1 = gate_act(a[1], actTanh);
                float v2 = gate_act(a[2], actTanh);
                float v3 = gate_act(a[3], actTanh);
                *reinterpret_cast<__half2*>(C + (size_t)row * PPD + col) =
                    __floats2half2_rn(v0, v1);
                *reinterpret_cast<__half2*>(C + (size_t)(row + 8) * PPD + col) =
                    __floats2half2_rn(v2, v3);
            } else {
                const float2 x0 = *reinterpret_cast<const float2*>(resid + (size_t)row * DD + col);
                const float2 x1 = *reinterpret_cast<const float2*>(resid + (size_t)(row + 8) * DD + col);
                *reinterpret_cast<float2*>(outp + (size_t)row * DD + col) =
                    make_float2(a[0] + x0.x, a[1] + x0.y);
                *reinterpret_cast<float2*>(outp + (size_t)(row + 8) * DD + col) =
                    make_float2(a[2] + x1.x, a[3] + x1.y);
            }
        }
    }
}

// ---------------- sequential scan over S (R10 config: 1 chain/thread, PF=16) -
__global__ void scan_kernel(int b, const float* __restrict__ h0, float* __restrict__ hfin) {
    int p = blockIdx.x * blockDim.x + threadIdx.x;
    if (p >= PD) return;
    float h = h0[(size_t)b * PD + p];
    size_t base = (size_t)b * SS * PPD + p;
    const __half* pi = g_gi + base;
    const __half* pf = g_gf + base;
    const __half* po = g_go + base;
    const __half* pc = g_gc + base;
    __half* pout = g_act + base;

    constexpr int PF = 16;
    __half bi[PF], bf[PF], bo[PF], bc[PF];
    #pragma unroll
    for (int j = 0; j < PF; ++j) {
        size_t o = (size_t)j * PPD;
        bi[j] = pi[o]; bf[j] = pf[o]; bo[j] = po[o]; bc[j] = pc[o];
    }
    #pragma unroll 16
    for (int s = 0; s < SS; ++s) {
        int slot = s & (PF - 1);
        float iv = __half2float(bi[slot]);
        float fv = __half2float(bf[slot]);
        float ov = __half2float(bo[slot]);
        float cv = __half2float(bc[slot]);
        int sn = s + PF;
        if (sn < SS) {
            size_t o = (size_t)sn * PPD;
            bi[slot] = pi[o]; bf[slot] = pf[o]; bo[slot] = po[o]; bc[slot] = pc[o];
        }
        h = fmaf(fv, h, iv * cv);                  // c already tanh'ed
        pout[(size_t)s * PPD] = __float2half_rn(ov * f_tanh(h));
    }
    if (hfin) hfin[(size_t)b * PD + p] = h;
}

// ---------------- streams/events (static init; fallback if creation fails) ---
struct Ctx {
    cudaStream_t s[4] = {};
    cudaEvent_t eF = nullptr, eW = nullptr, ePad = nullptr;
    cudaEvent_t eD[3] = {};
    bool ok = false;
    Ctx() {
        bool good = true;
        for (int i = 0; i < 4; ++i)
            good = good && (cudaStreamCreateWithFlags(&s[i], cudaStreamNonBlocking) == cudaSuccess);
        auto mk = [&](cudaEvent_t* e) {
            good = good && (cudaEventCreateWithFlags(e, cudaEventDisableTiming) == cudaSuccess);
        };
        mk(&eF); mk(&eW); mk(&ePad);
        for (int i = 0; i < 3; ++i) mk(&eD[i]);
        ok = good && (cudaDeviceSynchronize() == cudaSuccess);
    }
};
static Ctx g_ctx;

// ---------------- launch -----------------------------------------------------
extern "C" void kernel_launch(void* const* d_in, const int* in_sizes, int n_in,
                              void* d_out, int out_size) {
    const float* x    = (const float*)d_in[0];
    const float* h0   = (const float*)d_in[1];
    const float* Wi   = (const float*)d_in[2];
    const float* Wf   = (const float*)d_in[3];
    const float* Wo   = (const float*)d_in[4];
    const float* Wc   = (const float*)d_in[5];
    const float* Wout = (const float*)d_in[6];
    const float* lnw  = (const float*)d_in[7];
    float* out = (float*)d_out;
    float* hfin = nullptr;
    if (out_size >= BSD * DD + BB * PD) hfin = out + (size_t)BSD * DD;

    constexpr int SMEM_BYTES = 3 * 2 * 128 * 128;      // 98304 (3 stages, A+B)
    cudaFuncSetAttribute(gemm_fp16<0>, cudaFuncAttributeMaxDynamicSharedMemorySize, SMEM_BYTES);
    cudaFuncSetAttribute(gemm_fp16<1>, cudaFuncAttributeMaxDynamicSharedMemorySize, SMEM_BYTES);

    const int SCAN_GRID = (PD + 63) / 64;              // 43 blocks/batch

    if (!g_ctx.ok) {
        // ---- fallback: flat sequential path ----
        rmsnorm_kernel<<<BSD, 256>>>(x, lnw, 0);
        convert_w_kernel<<<dim3(((size_t)PD * DD / 4 + 255) / 256, 4), 256>>>(Wi, Wf, Wo, Wc);
        pad_wout_kernel<<<((size_t)DD * PPD / 4 + 255) / 256, 256>>>(Wout);
        gemm_fp16<0><<<dim3(PPD / 128, BSD / 128, 4), 256, SMEM_BYTES>>>(
            nullptr, nullptr, PD, DD / 64, DD, DD, 0);
        for (int b = 0; b < BB; ++b)
            scan_kernel<<<SCAN_GRID, 64>>>(b, h0, hfin);
        gemm_fp16<1><<<dim3(DD / 128, BSD / 128), 256, SMEM_BYTES>>>(
            x, out, DD, 43, PPD, PPD, 0);
        return;
    }

    cudaStream_t s0 = g_ctx.s[0], s1 = g_ctx.s[1], s2 = g_ctx.s[2], s3 = g_ctx.s[3];

    // ---- fork ----
    cudaEventRecord(g_ctx.eF, 0);
    cudaStreamWaitEvent(s0, g_ctx.eF, 0);
    cudaStreamWaitEvent(s1, g_ctx.eF, 0);
    cudaStreamWaitEvent(s2, g_ctx.eF, 0);
    cudaStreamWaitEvent(s3, g_ctx.eF, 0);

    // s3: weight converts -> eW; pad_wout -> ePad (only out-GEMMs need ePad)
    convert_w_kernel<<<dim3(((size_t)PD * DD / 4 + 255) / 256, 4), 256, 0, s3>>>(Wi, Wf, Wo, Wc);
    cudaEventRecord(g_ctx.eW, s3);
    pad_wout_kernel<<<((size_t)DD * PPD / 4 + 255) / 256, 256, 0, s3>>>(Wout);
    cudaEventRecord(g_ctx.ePad, s3);

    // ---- per-batch chains: rmsnorm_b -> gates_b -> scan_b -> out_b ----
    // batch 0 on default, batches 1..3 on s0..s2
    cudaStream_t chain[4] = { (cudaStream_t)0, s0, s1, s2 };
    for (int b = 0; b < BB; ++b) {
        cudaStream_t st = chain[b];
        rmsnorm_kernel<<<MB, 256, 0, st>>>(x, lnw, b * MB);
        cudaStreamWaitEvent(st, g_ctx.eW, 0);
        gemm_fp16<0><<<dim3(PPD / 128, MB / 128, 4), 256, SMEM_BYTES, st>>>(
            nullptr, nullptr, PD, DD / 64, DD, DD, b * MB);
        scan_kernel<<<SCAN_GRID, 64, 0, st>>>(b, h0, hfin);
        cudaStreamWaitEvent(st, g_ctx.ePad, 0);
        gemm_fp16<1><<<dim3(DD / 128, MB / 128), 256, SMEM_BYTES, st>>>(
            x, out, DD, 43, PPD, PPD, b * MB);
        if (b > 0) cudaEventRecord(g_ctx.eD[b - 1], st);
    }

    // ---- join ----
    for (int i = 0; i < 3; ++i)
        cudaStreamWaitEvent(0, g_ctx.eD[i], 0);
}

// round 17
// speedup vs baseline: 1.1553x; 1.0365x over previous
#include <cuda_runtime.h>
#include <cuda_fp16.h>
#include <cstdint>
#include <cstddef>

// Shapes: B=4, S=2048, D=2048, P=int(2048*1.333)=2729
#define BSD 8192
#define DD  2048
#define PD  2729
#define PPD 2816          // P padded to multiple of 128 (BN) and 64 (BK)
#define BB  4
#define SS  2048
#define MB  2048          // rows per batch (S)

// ---------------- scratch (device globals) ----------------------------------
__device__ __align__(256) __half g_xn [(size_t)BSD * DD];
__device__ __align__(256) __half g_wi [(size_t)PD * DD];
__device__ __align__(256) __half g_wf [(size_t)PD * DD];
__device__ __align__(256) __half g_wo [(size_t)PD * DD];
__device__ __align__(256) __half g_wc [(size_t)PD * DD];
__device__ __align__(256) __half g_wout[(size_t)DD * PPD];   // padded cols zeroed
__device__ __align__(256) __half g_gi [(size_t)BSD * PPD];
__device__ __align__(256) __half g_gf [(size_t)BSD * PPD];
__device__ __align__(256) __half g_go [(size_t)BSD * PPD];
__device__ __align__(256) __half g_gc [(size_t)BSD * PPD];
__device__ __align__(256) __half g_act[(size_t)BSD * PPD];   // pad cols stay 0 (zero-init)

// ---------------- PTX helpers ------------------------------------------------
__device__ __forceinline__ uint32_t smem_u32(const void* p) {
    uint32_t a;
    asm("{ .reg .u64 t; cvta.to.shared.u64 t, %1; cvt.u32.u64 %0, t; }" : "=r"(a) : "l"(p));
    return a;
}
__device__ __forceinline__ void cp16(uint32_t dst, const void* src, int nbytes) {
    asm volatile("cp.async.cg.shared.global [%0], [%1], 16, %2;\n"
                 :: "r"(dst), "l"(src), "r"(nbytes));
}
__device__ __forceinline__ void cp_commit() { asm volatile("cp.async.commit_group;\n"); }
template<int N> __device__ __forceinline__ void cp_wait() {
    asm volatile("cp.async.wait_group %0;\n" :: "n"(N) : "memory");
}
__device__ __forceinline__ void ldsm4(uint32_t* r, uint32_t addr) {
    asm volatile("ldmatrix.sync.aligned.m8n8.x4.shared.b16 {%0,%1,%2,%3}, [%4];"
                 : "=r"(r[0]), "=r"(r[1]), "=r"(r[2]), "=r"(r[3]) : "r"(addr));
}
// m16n8k16 fp16 in, fp32 accum
__device__ __forceinline__ void mma16(float* c, const uint32_t* a, const uint32_t* b) {
    asm volatile(
        "mma.sync.aligned.m16n8k16.row.col.f32.f16.f16.f32 "
        "{%0,%1,%2,%3}, {%4,%5,%6,%7}, {%8,%9}, {%0,%1,%2,%3};\n"
        : "+f"(c[0]), "+f"(c[1]), "+f"(c[2]), "+f"(c[3])
        : "r"(a[0]), "r"(a[1]), "r"(a[2]), "r"(a[3]), "r"(b[0]), "r"(b[1]));
}

// ---------------- fast activations -------------------------------------------
__device__ __forceinline__ float f_ex2(float x) { float y; asm("ex2.approx.f32 %0, %1;" : "=f"(y) : "f"(x)); return y; }
__device__ __forceinline__ float f_rcp(float x) { float y; asm("rcp.approx.f32 %0, %1;" : "=f"(y) : "f"(x)); return y; }
__device__ __forceinline__ float f_tanh(float x) {
    x = fminf(fmaxf(x, -15.f), 15.f);
    float u = f_ex2(x * 2.885390082f);             // e^{2x}
    return (u - 1.f) * f_rcp(u + 1.f);
}
__device__ __forceinline__ float f_sig(float x) {
    float v = f_ex2(-x * 1.442695041f);
    return f_rcp(1.f + v);
}
__device__ __forceinline__ float gate_act(float z, bool tanhOnly) {
    if (tanhOnly) return f_tanh(z);
    float t = 15.f * f_tanh(z * (1.f / 15.f));     // soft cap
    return f_sig(t);
}

// ---------------- rmsnorm -> fp16 (per-batch: rowbase) -----------------------
__global__ void rmsnorm_kernel(const float* __restrict__ x, const float* __restrict__ w,
                               int rowbase) {
    int row = rowbase + blockIdx.x;
    int t = threadIdx.x;
    const float4* xr = reinterpret_cast<const float4*>(x + (size_t)row * DD);
    float4 v0 = xr[t], v1 = xr[t + 256];
    float ss = v0.x*v0.x + v0.y*v0.y + v0.z*v0.z + v0.w*v0.w
             + v1.x*v1.x + v1.y*v1.y + v1.z*v1.z + v1.w*v1.w;
    #pragma unroll
    for (int o = 16; o > 0; o >>= 1) ss += __shfl_xor_sync(0xffffffffu, ss, o);
    __shared__ float red[8];
    if ((t & 31) == 0) red[t >> 5] = ss;
    __syncthreads();
    float tot = red[0]+red[1]+red[2]+red[3]+red[4]+red[5]+red[6]+red[7];
    float r = rsqrtf(tot * (1.0f / DD) + 1e-6f);
    const float4* wr = reinterpret_cast<const float4*>(w);
    float4 w0 = wr[t], w1 = wr[t + 256];
    __half2* dst = reinterpret_cast<__half2*>(g_xn + (size_t)row * DD);
    dst[t*2  ]       = __floats2half2_rn(v0.x*r*w0.x, v0.y*r*w0.y);
    dst[t*2+1]       = __floats2half2_rn(v0.z*r*w0.z, v0.w*r*w0.w);
    dst[(t+256)*2  ] = __floats2half2_rn(v1.x*r*w1.x, v1.y*r*w1.y);
    dst[(t+256)*2+1] = __floats2half2_rn(v1.z*r*w1.z, v1.w*r*w1.w);
}

// ---------------- weight conversion (vectorized) -----------------------------
__global__ void convert_w_kernel(const float* __restrict__ W0, const float* __restrict__ W1,
                                 const float* __restrict__ W2, const float* __restrict__ W3) {
    size_t i4 = (size_t)blockIdx.x * blockDim.x + threadIdx.x;
    if (i4 >= (size_t)PD * DD / 4) return;
    int z = blockIdx.y;
    const float* src = (z == 0) ? W0 : (z == 1) ? W1 : (z == 2) ? W2 : W3;
    __half* dst = (z == 0) ? g_wi : (z == 1) ? g_wf : (z == 2) ? g_wo : g_wc;
    float4 v = reinterpret_cast<const float4*>(src)[i4];
    __half2 h0 = __floats2half2_rn(v.x, v.y);
    __half2 h1 = __floats2half2_rn(v.z, v.w);
    *reinterpret_cast<uint2*>(dst + i4 * 4) =
        make_uint2(*reinterpret_cast<uint32_t*>(&h0), *reinterpret_cast<uint32_t*>(&h1));
}
__global__ void pad_wout_kernel(const float* __restrict__ wout) {
    size_t i4 = (size_t)blockIdx.x * blockDim.x + threadIdx.x;
    if (i4 >= (size_t)DD * PPD / 4) return;
    int d = (int)(i4 / (PPD / 4));
    int p = (int)(i4 % (PPD / 4)) * 4;
    const float* src = wout + (size_t)d * PD + p;
    float a0 = (p     < PD) ? src[0] : 0.f;
    float a1 = (p + 1 < PD) ? src[1] : 0.f;
    float a2 = (p + 2 < PD) ? src[2] : 0.f;
    float a3 = (p + 3 < PD) ? src[3] : 0.f;
    __half2 h0 = __floats2half2_rn(a0, a1);
    __half2 h1 = __floats2half2_rn(a2, a3);
    *reinterpret_cast<uint2*>(g_wout + i4 * 4) =
        make_uint2(*reinterpret_cast<uint32_t*>(&h0), *reinterpret_cast<uint32_t*>(&h1));
}

// ---------------- fp16 TN GEMM (R10 config: 8 warps 4x2 of 32x64) ------------
// XOR-swizzled smem rows (128B): chunk c of row r at r*128 + ((c^(r&7))<<4).
// MODE 0 (gates): z = blockIdx.z, flat half2-plane stores.
// MODE 1 (out): mbase = first output row (per-batch launches).
template<int MODE>
__global__ __launch_bounds__(256, 2)
void gemm_fp16(const float* __restrict__ resid, float* __restrict__ outp,
               int Nreal, int KT, int lda, int ldb, int mbase)
{
    constexpr int BM = 128, BN = 128, BK = 64;
    constexpr int TILE_B = BM * 128;        // 16384 bytes per tile (A or B)
    constexpr int STG = 2 * TILE_B;         // 32768 bytes per stage
    extern __shared__ char dsm[];

    const int tid  = threadIdx.x;
    const int lane = tid & 31;
    const int wid  = tid >> 5;
    const int wm   = wid & 3;               // 4 warps along M (32 rows)
    const int wn   = wid >> 2;              // 2 warps along N (64 cols)
    const int m0   = mbase + blockIdx.y * BM;
    const int n0   = blockIdx.x * BN;

    const __half* A;
    const __half* Bw;
    __half* C = nullptr;
    bool actTanh = false;
    if (MODE == 0) {
        A = g_xn;
        int z = blockIdx.z;
        Bw = (z == 0) ? g_wi : (z == 1) ? g_wf : (z == 2) ? g_wo : g_wc;
        C  = (z == 0) ? g_gi : (z == 1) ? g_gf : (z == 2) ? g_go : g_gc;
        actTanh = (z == 3);
    } else {
        A = g_act; Bw = g_wout;
    }

    const uint32_t sbase = smem_u32(dsm);

    // ---- fill() invariants ---------------------------------------------------
    const int tr = tid >> 3;                 // base row 0..31
    const int tc = tid & 7;                  // 16B chunk, constant
    const uint32_t offS = (uint32_t)(tr * 128 + ((tc ^ (tr & 7)) << 4));
    const __half* pA = A + (size_t)(m0 + tr) * lda + tc * 8;
    int nb[4];
    size_t dB[4];
    #pragma unroll
    for (int i = 0; i < 4; ++i) {
        int r = n0 + tr + i * 32;
        int ok = (MODE == 1) || (r < Nreal);
        nb[i] = ok ? 16 : 0;
        dB[i] = (size_t)(ok ? (size_t)i * 32 * ldb : 0);
    }
    const __half* pB = Bw + (size_t)(n0 + tr) * ldb + tc * 8;

    auto fill = [&](uint32_t stg) {
        uint32_t ab = stg + offS;
        #pragma unroll
        for (int i = 0; i < 4; ++i)
            cp16(ab + i * 4096, pA + (size_t)i * 32 * lda, 16);
        uint32_t bb = ab + TILE_B;
        #pragma unroll
        for (int i = 0; i < 4; ++i)
            cp16(bb + i * 4096, pB + dB[i], nb[i]);
        cp_commit();
        pA += BK;
        pB += BK;
    };

    float acc[2][8][4];
    #pragma unroll
    for (int im = 0; im < 2; ++im)
        #pragma unroll
        for (int in = 0; in < 8; ++in)
            #pragma unroll
            for (int j = 0; j < 4; ++j) acc[im][in][j] = 0.0f;

    // ---- precomputed ldmatrix addresses --------------------------------------
    const int l7 = lane & 7, l6 = lane & 6, l1 = lane & 1;
    const int a_row = ((lane >> 3) & 1) * 8 + l7;
    const int a_ch  = (lane >> 4);                   // 0/1
    const int b_row = ((lane >> 4) & 1) * 8 + l7;
    const int b_ch  = (lane >> 3) & 1;
    uint32_t baseA[2], baseB[4], dks[4];
    #pragma unroll
    for (int im = 0; im < 2; ++im)
        baseA[im] = (uint32_t)((wm * 32 + im * 16 + a_row) * 128 + ((a_ch ^ l1) << 4));
    #pragma unroll
    for (int ip = 0; ip < 4; ++ip)
        baseB[ip] = (uint32_t)(TILE_B + (wn * 64 + ip * 16 + b_row) * 128 + ((b_ch ^ l1) << 4));
    #pragma unroll
    for (int ks = 0; ks < 4; ++ks)
        dks[ks] = (uint32_t)(((2 * ks) ^ l6) << 4);

    const uint32_t stg0 = sbase, stg1 = sbase + STG, stg2 = sbase + 2 * STG;

    fill(stg0);
    fill(stg1);
    cp_wait<1>();
    __syncthreads();

    int s = 0, sf = 2;          // current stage id, next-fill stage id
    for (int kt = 0; kt < KT; ++kt) {
        if (kt + 2 < KT) {
            fill(sf == 0 ? stg0 : sf == 1 ? stg1 : stg2);
            if (++sf == 3) sf = 0;
        } else cp_commit();

        const uint32_t stA = (s == 0) ? stg0 : (s == 1) ? stg1 : stg2;

        #pragma unroll
        for (int ks = 0; ks < 4; ++ks) {
            const uint32_t d = dks[ks];
            uint32_t ra[2][4];
            #pragma unroll
            for (int im = 0; im < 2; ++im)
                ldsm4(ra[im], stA + baseA[im] + d);
            #pragma unroll
            for (int ip = 0; ip < 4; ++ip) {
                uint32_t r4[4];
                ldsm4(r4, stA + baseB[ip] + d);
                #pragma unroll
                for (int im = 0; im < 2; ++im) {
                    mma16(acc[im][2*ip    ], ra[im], r4);
                    mma16(acc[im][2*ip + 1], ra[im], r4 + 2);
                }
            }
        }
        cp_wait<1>();
        __syncthreads();
        if (++s == 3) s = 0;
    }

    // ---- epilogue ------------------------------------------------------------
    const int qr = lane >> 2;
    const int qc = lane & 3;
    #pragma unroll
    for (int im = 0; im < 2; ++im) {
        int row = m0 + wm * 32 + im * 16 + qr;
        #pragma unroll
        for (int in = 0; in < 8; ++in) {
            int col = n0 + wn * 64 + in * 8 + qc * 2;
            float* a = acc[im][in];
            if (MODE == 0) {
                float v0 = gate_act(a[0], actTanh);
                float v1 = gate_act(a[1], actTanh);
                float v2 = gate_act(a[2], actTanh);
                float v3 = gate_act(a[3], actTanh);
                *reinterpret_cast<__half2*>(C + (size_t)row * PPD + col) =
                    __floats2half2_rn(v0, v1);
                *reinterpret_cast<__half2*>(C + (size_t)(row + 8) * PPD + col) =
                    __floats2half2_rn(v2, v3);
            } else {
                const float2 x0 = *reinterpret_cast<const float2*>(resid + (size_t)row * DD + col);
                const float2 x1 = *reinterpret_cast<const float2*>(resid + (size_t)(row + 8) * DD + col);
                *reinterpret_cast<float2*>(outp + (size_t)row * DD + col) =
                    make_float2(a[0] + x0.x, a[1] + x0.y);
                *reinterpret_cast<float2*>(outp + (size_t)(row + 8) * DD + col) =
                    make_float2(a[2] + x1.x, a[3] + x1.y);
            }
        }
    }
}

// ---------------- sequential scan over S (1 chain/thread, PF=32) -------------
// PF=32 widens the load-consume window to ~640 cyc > 577-cyc DRAM latency,
// flipping the scan from latency-bound to issue-bound.
__global__ void scan_kernel(int b, const float* __restrict__ h0, float* __restrict__ hfin) {
    int p = blockIdx.x * blockDim.x + threadIdx.x;
    if (p >= PD) return;
    float h = h0[(size_t)b * PD + p];
    size_t base = (size_t)b * SS * PPD + p;
    const __half* pi = g_gi + base;
    const __half* pf = g_gf + base;
    const __half* po = g_go + base;
    const __half* pc = g_gc + base;
    __half* pout = g_act + base;

    constexpr int PF = 32;
    __half bi[PF], bf[PF], bo[PF], bc[PF];
    #pragma unroll
    for (int j = 0; j < PF; ++j) {
        size_t o = (size_t)j * PPD;
        bi[j] = pi[o]; bf[j] = pf[o]; bo[j] = po[o]; bc[j] = pc[o];
    }
    #pragma unroll 32
    for (int s = 0; s < SS; ++s) {
        int slot = s & (PF - 1);
        float iv = __half2float(bi[slot]);
        float fv = __half2float(bf[slot]);
        float ov = __half2float(bo[slot]);
        float cv = __half2float(bc[slot]);
        int sn = s + PF;
        if (sn < SS) {
            size_t o = (size_t)sn * PPD;
            bi[slot] = pi[o]; bf[slot] = pf[o]; bo[slot] = po[o]; bc[slot] = pc[o];
        }
        h = fmaf(fv, h, iv * cv);                  // c already tanh'ed
        pout[(size_t)s * PPD] = __float2half_rn(ov * f_tanh(h));
    }
    if (hfin) hfin[(size_t)b * PD + p] = h;
}

// ---------------- streams/events (static init; fallback if creation fails) ---
struct Ctx {
    cudaStream_t s[4] = {};
    cudaEvent_t eF = nullptr, eW = nullptr, ePad = nullptr;
    cudaEvent_t eD[3] = {};
    bool ok = false;
    Ctx() {
        bool good = true;
        for (int i = 0; i < 4; ++i)
            good = good && (cudaStreamCreateWithFlags(&s[i], cudaStreamNonBlocking) == cudaSuccess);
        auto mk = [&](cudaEvent_t* e) {
            good = good && (cudaEventCreateWithFlags(e, cudaEventDisableTiming) == cudaSuccess);
        };
        mk(&eF); mk(&eW); mk(&ePad);
        for (int i = 0; i < 3; ++i) mk(&eD[i]);
        ok = good && (cudaDeviceSynchronize() == cudaSuccess);
    }
};
static Ctx g_ctx;

// ---------------- launch -----------------------------------------------------
extern "C" void kernel_launch(void* const* d_in, const int* in_sizes, int n_in,
                              void* d_out, int out_size) {
    const float* x    = (const float*)d_in[0];
    const float* h0   = (const float*)d_in[1];
    const float* Wi   = (const float*)d_in[2];
    const float* Wf   = (const float*)d_in[3];
    const float* Wo   = (const float*)d_in[4];
    const float* Wc   = (const float*)d_in[5];
    const float* Wout = (const float*)d_in[6];
    const float* lnw  = (const float*)d_in[7];
    float* out = (float*)d_out;
    float* hfin = nullptr;
    if (out_size >= BSD * DD + BB * PD) hfin = out + (size_t)BSD * DD;

    constexpr int SMEM_BYTES = 3 * 2 * 128 * 128;      // 98304 (3 stages, A+B)
    cudaFuncSetAttribute(gemm_fp16<0>, cudaFuncAttributeMaxDynamicSharedMemorySize, SMEM_BYTES);
    cudaFuncSetAttribute(gemm_fp16<1>, cudaFuncAttributeMaxDynamicSharedMemorySize, SMEM_BYTES);

    const int SCAN_GRID = (PD + 63) / 64;              // 43 blocks/batch

    if (!g_ctx.ok) {
        // ---- fallback: flat sequential path ----
        rmsnorm_kernel<<<BSD, 256>>>(x, lnw, 0);
        convert_w_kernel<<<dim3(((size_t)PD * DD / 4 + 255) / 256, 4), 256>>>(Wi, Wf, Wo, Wc);
        pad_wout_kernel<<<((size_t)DD * PPD / 4 + 255) / 256, 256>>>(Wout);
        gemm_fp16<0><<<dim3(PPD / 128, BSD / 128, 4), 256, SMEM_BYTES>>>(
            nullptr, nullptr, PD, DD / 64, DD, DD, 0);
        for (int b = 0; b < BB; ++b)
            scan_kernel<<<SCAN_GRID, 64>>>(b, h0, hfin);
        gemm_fp16<1><<<dim3(DD / 128, BSD / 128), 256, SMEM_BYTES>>>(
            x, out, DD, 43, PPD, PPD, 0);
        return;
    }

    cudaStream_t s0 = g_ctx.s[0], s1 = g_ctx.s[1], s2 = g_ctx.s[2], s3 = g_ctx.s[3];

    // ---- fork ----
    cudaEventRecord(g_ctx.eF, 0);
    cudaStreamWaitEvent(s0, g_ctx.eF, 0);
    cudaStreamWaitEvent(s1, g_ctx.eF, 0);
    cudaStreamWaitEvent(s2, g_ctx.eF, 0);
    cudaStreamWaitEvent(s3, g_ctx.eF, 0);

    // s3: weight converts -> eW; pad_wout -> ePad (only out-GEMMs need ePad)
    convert_w_kernel<<<dim3(((size_t)PD * DD / 4 + 255) / 256, 4), 256, 0, s3>>>(Wi, Wf, Wo, Wc);
    cudaEventRecord(g_ctx.eW, s3);
    pad_wout_kernel<<<((size_t)DD * PPD / 4 + 255) / 256, 256, 0, s3>>>(Wout);
    cudaEventRecord(g_ctx.ePad, s3);

    // ---- per-batch chains: rmsnorm_b -> gates_b -> scan_b -> out_b ----
    cudaStream_t chain[4] = { (cudaStream_t)0, s0, s1, s2 };
    for (int b = 0; b < BB; ++b) {
        cudaStream_t st = chain[b];
        rmsnorm_kernel<<<MB, 256, 0, st>>>(x, lnw, b * MB);
        cudaStreamWaitEvent(st, g_ctx.eW, 0);
        gemm_fp16<0><<<dim3(PPD / 128, MB / 128, 4), 256, SMEM_BYTES, st>>>(
            nullptr, nullptr, PD, DD / 64, DD, DD, b * MB);
        scan_kernel<<<SCAN_GRID, 64, 0, st>>>(b, h0, hfin);
        cudaStreamWaitEvent(st, g_ctx.ePad, 0);
        gemm_fp16<1><<<dim3(DD / 128, MB / 128), 256, SMEM_BYTES, st>>>(
            x, out, DD, 43, PPD, PPD, b * MB);
        if (b > 0) cudaEventRecord(g_ctx.eD[b - 1], st);
    }

    // ---- join ----
    for (int i = 0; i < 3; ++i)
        cudaStreamWaitEvent(0, g_ctx.eD[i], 0);
}